// round 13
// baseline (speedup 1.0000x reference)
#include <cuda_runtime.h>
#include <cuda_fp16.h>
#include <stdint.h>

#define MAXN 100000
#define MAXE 1600000
#define PAD  64
#define OUTD 256

// ---------------- scratch (device globals; no runtime allocation) ----------------
__device__ int    g_cnt[MAXN];
__device__ int    g_csr[(size_t)MAXN * PAD];
__device__ float  g_dinv[MAXN];
__device__ float  g_xw[(size_t)MAXN * OUTD];    // GEMM output (gather operand), fp32
__device__ float  g_iden[(size_t)MAXN * OUTD];  // projection x@Wp + bp
__device__ float  g_h1[(size_t)MAXN * OUTD];    // relu(conv1), GEMM2 input

// ---------------- small setup kernels ----------------
__global__ void zero_cnt_kernel(int n) {
    int i = blockIdx.x * blockDim.x + threadIdx.x;
    if (i < n) g_cnt[i] = 0;
}

// Build padded CSR grouped by destination. int64 vs int32 detection: if data is
// int64 the high dword of every 8-byte word is 0 (values < N); if int32 the high
// dwords contain edge entries (nonzero across 16 words w.h.p.).
__global__ void fill_csr_kernel(const void* __restrict__ edge, int E) {
    const unsigned long long* p64 = (const unsigned long long*)edge;
    unsigned long long hi = 0ull;
#pragma unroll
    for (int i = 0; i < 16; i++) hi |= (p64[i] >> 32);
    const bool is64 = (hi == 0ull);
    const long long* e64 = (const long long*)edge;
    const int*       e32 = (const int*)edge;

    for (int e = blockIdx.x * blockDim.x + threadIdx.x; e < E;
         e += gridDim.x * blockDim.x) {
        int s, d;
        if (is64) { s = (int)e64[e]; d = (int)e64[e + E]; }
        else      { s = e32[e];      d = e32[e + E]; }
        int slot = atomicAdd(&g_cnt[d], 1);
        if (slot < PAD) g_csr[(size_t)d * PAD + slot] = s;
    }
}

__global__ void dinv_kernel(int n) {
    int i = blockIdx.x * blockDim.x + threadIdx.x;
    if (i < n) g_dinv[i] = rsqrtf((float)(g_cnt[i] + 1));  // +1 self-loop
}

// ---------------- SGEMM: C[M,N] = A[M,K] @ B[K,N] (+ bias) ----------------
// BM=BN=128, BK=16, 256 threads, 8x8 microtile, register prefetch. fp32.
#define BM 128
#define BN 128
#define BK 16

__global__ __launch_bounds__(256, 2)
void sgemm_kernel(const float* __restrict__ A, const float* __restrict__ B,
                  const float* __restrict__ bias, float* __restrict__ C,
                  int M, int K, int N) {
    __shared__ float As[BK][BM + 4];
    __shared__ float Bs[BK][BN];

    const int tid = threadIdx.x;
    const int tx  = tid & 15;
    const int ty  = tid >> 4;
    const int rowBase = blockIdx.x * BM;
    const int colBase = blockIdx.y * BN;

    const int ar = tid >> 2;
    const int ac = (tid & 3) * 4;
    const int br = tid >> 5;
    const int bc = (tid & 31) * 4;

    const bool av0 = (rowBase + ar)      < M;
    const bool av1 = (rowBase + ar + 64) < M;

    const float* Ap0 = A + (size_t)(rowBase + ar) * K + ac;
    const float* Ap1 = Ap0 + (size_t)64 * K;

    float acc[8][8];
#pragma unroll
    for (int i = 0; i < 8; i++)
#pragma unroll
        for (int j = 0; j < 8; j++) acc[i][j] = 0.0f;

    const float4 zero4 = make_float4(0.f, 0.f, 0.f, 0.f);

    float4 pa0 = av0 ? *(const float4*)Ap0 : zero4;
    float4 pa1 = av1 ? *(const float4*)Ap1 : zero4;
    float4 pb0 = *(const float4*)(B + (size_t)br * N + colBase + bc);
    float4 pb1 = *(const float4*)(B + (size_t)(br + 8) * N + colBase + bc);

    int k0 = 0;
    while (true) {
        As[ac + 0][ar] = pa0.x; As[ac + 1][ar] = pa0.y;
        As[ac + 2][ar] = pa0.z; As[ac + 3][ar] = pa0.w;
        As[ac + 0][ar + 64] = pa1.x; As[ac + 1][ar + 64] = pa1.y;
        As[ac + 2][ar + 64] = pa1.z; As[ac + 3][ar + 64] = pa1.w;
        *(float4*)&Bs[br][bc]     = pb0;
        *(float4*)&Bs[br + 8][bc] = pb1;
        __syncthreads();

        k0 += BK;
        const bool more = (k0 < K);
        if (more) {
            pa0 = av0 ? *(const float4*)(Ap0 + k0) : zero4;
            pa1 = av1 ? *(const float4*)(Ap1 + k0) : zero4;
            pb0 = *(const float4*)(B + (size_t)(k0 + br) * N + colBase + bc);
            pb1 = *(const float4*)(B + (size_t)(k0 + br + 8) * N + colBase + bc);
        }

#pragma unroll
        for (int kk = 0; kk < BK; kk++) {
            float4 ra0 = *(const float4*)&As[kk][ty * 4];
            float4 ra1 = *(const float4*)&As[kk][ty * 4 + 64];
            float4 rb0 = *(const float4*)&Bs[kk][tx * 4];
            float4 rb1 = *(const float4*)&Bs[kk][tx * 4 + 64];
            float av[8] = {ra0.x, ra0.y, ra0.z, ra0.w, ra1.x, ra1.y, ra1.z, ra1.w};
            float bv[8] = {rb0.x, rb0.y, rb0.z, rb0.w, rb1.x, rb1.y, rb1.z, rb1.w};
#pragma unroll
            for (int i = 0; i < 8; i++)
#pragma unroll
                for (int j = 0; j < 8; j++)
                    acc[i][j] = fmaf(av[i], bv[j], acc[i][j]);
        }

        if (!more) break;
        __syncthreads();
    }

    float4 bv0 = zero4, bv1 = zero4;
    if (bias) {
        bv0 = *(const float4*)(bias + colBase + tx * 4);
        bv1 = *(const float4*)(bias + colBase + tx * 4 + 64);
    }
#pragma unroll
    for (int half = 0; half < 2; half++) {
#pragma unroll
        for (int i = 0; i < 4; i++) {
            int grow = rowBase + half * 64 + ty * 4 + i;
            if (grow >= M) continue;
            int ii = half * 4 + i;
            float4 o0, o1;
            o0.x = acc[ii][0] + bv0.x; o0.y = acc[ii][1] + bv0.y;
            o0.z = acc[ii][2] + bv0.z; o0.w = acc[ii][3] + bv0.w;
            o1.x = acc[ii][4] + bv1.x; o1.y = acc[ii][5] + bv1.y;
            o1.z = acc[ii][6] + bv1.z; o1.w = acc[ii][7] + bv1.w;
            *(float4*)(C + (size_t)grow * N + colBase + tx * 4)      = o0;
            *(float4*)(C + (size_t)grow * N + colBase + tx * 4 + 64) = o1;
        }
    }
}

// ---------------- aggregation: one warp per node, fp32 + packed f32x2 FMA ----------------
// Issue-bound fix: per edge-lane = 2x LDG.128 + 1 weight pack + 4x FFMA2 for all
// 8 owned columns (single pass over 256 cols). No converts.
#define FFMA2(acc, v, w2) \
    asm("fma.rn.f32x2 %0, %1, %2, %0;" : "+l"(acc) : "l"(v), "l"(w2))
#define PACK2(dst, s) \
    asm("mov.b64 %0, {%1, %1};" : "=l"(dst) : "r"(__float_as_uint(s)))

__global__ __launch_bounds__(256)
void aggregate_kernel(const float* __restrict__ xw,
                      const float* __restrict__ bias,
                      const float* __restrict__ resid,  // nullable
                      float* __restrict__ out, int n) {
    __shared__ int   shI[8][PAD + 2];
    __shared__ float shW[8][PAD + 2];

    const int wslot = threadIdx.x >> 5;
    const int w     = (blockIdx.x * blockDim.x + threadIdx.x) >> 5;
    const int lane  = threadIdx.x & 31;
    if (w >= n) return;

    const float di = g_dinv[w];
    int c = g_cnt[w];
    if (c > PAD) c = PAD;

    // Stage metadata (coalesced); self-loop appended as last entry.
    const int* ep = g_csr + (size_t)w * PAD;
#pragma unroll
    for (int r = 0; r < PAD / 32; r++) {
        int j = r * 32 + lane;
        if (j < c) {
            int s = ep[j];
            shI[wslot][j] = s;
            shW[wslot][j] = g_dinv[s] * di;
        }
    }
    if (lane == 0) { shI[wslot][c] = w; shW[wslot][c] = di * di; }
    __syncwarp();
    const int tot = c + 1;

    const size_t colOff = (size_t)lane * 8;   // 8 consecutive floats per lane
    unsigned long long a0 = 0, a1 = 0, a2 = 0, a3 = 0;  // 4x f32x2 accumulators

    const int*   shi = shI[wslot];
    const float* shw = shW[wslot];

    int j = 0;
    for (; j + 2 <= tot; j += 2) {
        int s0 = shi[j], s1 = shi[j + 1];
        unsigned long long w20, w21;
        PACK2(w20, shw[j]);
        PACK2(w21, shw[j + 1]);
        const ulonglong2* p0 = (const ulonglong2*)(xw + (size_t)s0 * OUTD + colOff);
        const ulonglong2* p1 = (const ulonglong2*)(xw + (size_t)s1 * OUTD + colOff);
        ulonglong2 u00 = p0[0], u01 = p0[1];
        ulonglong2 u10 = p1[0], u11 = p1[1];
        FFMA2(a0, u00.x, w20); FFMA2(a1, u00.y, w20);
        FFMA2(a2, u01.x, w20); FFMA2(a3, u01.y, w20);
        FFMA2(a0, u10.x, w21); FFMA2(a1, u10.y, w21);
        FFMA2(a2, u11.x, w21); FFMA2(a3, u11.y, w21);
    }
    if (j < tot) {
        int s0 = shi[j];
        unsigned long long w20;
        PACK2(w20, shw[j]);
        const ulonglong2* p0 = (const ulonglong2*)(xw + (size_t)s0 * OUTD + colOff);
        ulonglong2 u00 = p0[0], u01 = p0[1];
        FFMA2(a0, u00.x, w20); FFMA2(a1, u00.y, w20);
        FFMA2(a2, u01.x, w20); FFMA2(a3, u01.y, w20);
    }

    // Unpack accumulators.
    float acc[8];
    asm("mov.b64 {%0, %1}, %2;" : "=f"(acc[0]), "=f"(acc[1]) : "l"(a0));
    asm("mov.b64 {%0, %1}, %2;" : "=f"(acc[2]), "=f"(acc[3]) : "l"(a1));
    asm("mov.b64 {%0, %1}, %2;" : "=f"(acc[4]), "=f"(acc[5]) : "l"(a2));
    asm("mov.b64 {%0, %1}, %2;" : "=f"(acc[6]), "=f"(acc[7]) : "l"(a3));

    float4 b0 = *(const float4*)(bias + colOff);
    float4 b1 = *(const float4*)(bias + colOff + 4);
    acc[0] += b0.x; acc[1] += b0.y; acc[2] += b0.z; acc[3] += b0.w;
    acc[4] += b1.x; acc[5] += b1.y; acc[6] += b1.z; acc[7] += b1.w;

    if (resid) {
        float4 q0 = *(const float4*)(resid + (size_t)w * OUTD + colOff);
        float4 q1 = *(const float4*)(resid + (size_t)w * OUTD + colOff + 4);
        acc[0] += q0.x; acc[1] += q0.y; acc[2] += q0.z; acc[3] += q0.w;
        acc[4] += q1.x; acc[5] += q1.y; acc[6] += q1.z; acc[7] += q1.w;
    }

#pragma unroll
    for (int k = 0; k < 8; k++) acc[k] = fmaxf(acc[k], 0.f);

    *(float4*)(out + (size_t)w * OUTD + colOff)     = make_float4(acc[0], acc[1], acc[2], acc[3]);
    *(float4*)(out + (size_t)w * OUTD + colOff + 4) = make_float4(acc[4], acc[5], acc[6], acc[7]);
}

// ---------------- launch ----------------
extern "C" void kernel_launch(void* const* d_in, const int* in_sizes, int n_in,
                              void* d_out, int out_size) {
    const float* x  = (const float*)d_in[0];
    const void*  ei = d_in[1];
    const float* W1 = (const float*)d_in[2];
    const float* b1 = (const float*)d_in[3];
    const float* W2 = (const float*)d_in[4];
    const float* b2 = (const float*)d_in[5];
    const float* Wp = (const float*)d_in[6];
    const float* bp = (const float*)d_in[7];
    float* out = (float*)d_out;

    int ind = in_sizes[2] / OUTD;     // W1 is [IN, 256]
    int n   = in_sizes[0] / ind;      // nodes
    int E   = in_sizes[1] / 2;        // edges
    if (n > MAXN) n = MAXN;
    if (E > MAXE) E = MAXE;

    float *xw, *iden, *h1;
    cudaGetSymbolAddress((void**)&xw,   g_xw);
    cudaGetSymbolAddress((void**)&iden, g_iden);
    cudaGetSymbolAddress((void**)&h1,   g_h1);

    // 1. build padded CSR + degrees
    zero_cnt_kernel<<<(n + 255) / 256, 256>>>(n);
    fill_csr_kernel<<<(E + 255) / 256, 256>>>(ei, E);
    dinv_kernel<<<(n + 255) / 256, 256>>>(n);

    dim3 g1((n + BM - 1) / BM, OUTD / BN);
    int aggBlocks = (n * 32 + 255) / 256;

    // 2. XW1 and projection
    sgemm_kernel<<<g1, 256>>>(x, W1, nullptr, xw,   n, ind, OUTD);
    sgemm_kernel<<<g1, 256>>>(x, Wp, bp,      iden, n, ind, OUTD);

    // 3. conv1 aggregation + b1 + relu -> h1
    aggregate_kernel<<<aggBlocks, 256>>>(xw, b1, nullptr, h1, n);

    // 4. H1 @ W2
    sgemm_kernel<<<g1, 256>>>(h1, W2, nullptr, xw, n, OUTD, OUTD);

    // 5. conv2 aggregation + b2 + identity + relu -> out
    aggregate_kernel<<<aggBlocks, 256>>>(xw, b2, iden, out, n);
}

// round 14
// speedup vs baseline: 2.2806x; 2.2806x over previous
#include <cuda_runtime.h>
#include <cuda_fp16.h>
#include <stdint.h>

#define MAXN 100000
#define MAXE 1600000
#define PAD  64
#define OUTD 256
#define MAXIN 128

// ---------------- scratch (device globals; no runtime allocation) ----------------
__device__ int    g_cnt[MAXN];
__device__ int    g_csr[(size_t)MAXN * PAD];
__device__ float  g_dinv[MAXN];
__device__ __half g_xwh[(size_t)MAXN * OUTD];    // fp16 GEMM output (gather operand)
__device__ __half g_idenh[(size_t)MAXN * OUTD];  // fp16 projection x@Wp + bp
__device__ __half g_h1h[(size_t)MAXN * OUTD];    // fp16 relu(conv1), GEMM2 input
__device__ __half g_xh[(size_t)MAXN * MAXIN];    // fp16 copy of x
__device__ __half g_W1h[MAXIN * OUTD];
__device__ __half g_W2h[OUTD * OUTD];
__device__ __half g_Wph[MAXIN * OUTD];

// ---------------- small setup kernels ----------------
__global__ void zero_cnt_kernel(int n) {
    int i = blockIdx.x * blockDim.x + threadIdx.x;
    if (i < n) g_cnt[i] = 0;
}

__global__ void f2h_kernel(const float* __restrict__ src, __half* __restrict__ dst, int count4) {
    int i = blockIdx.x * blockDim.x + threadIdx.x;
    if (i < count4) {
        float4 v = *(const float4*)(src + 4 * (size_t)i);
        __half2 h0 = __floats2half2_rn(v.x, v.y);
        __half2 h1 = __floats2half2_rn(v.z, v.w);
        uint2 u; u.x = *(unsigned*)&h0; u.y = *(unsigned*)&h1;
        *(uint2*)(dst + 4 * (size_t)i) = u;
    }
}

// Build padded CSR grouped by destination. int64 vs int32 detection: if data is
// int64 the high dword of every 8-byte word is 0 (values < N); if int32 the high
// dwords contain edge entries (nonzero across 16 words w.h.p.).
__global__ void fill_csr_kernel(const void* __restrict__ edge, int E) {
    const unsigned long long* p64 = (const unsigned long long*)edge;
    unsigned long long hi = 0ull;
#pragma unroll
    for (int i = 0; i < 16; i++) hi |= (p64[i] >> 32);
    const bool is64 = (hi == 0ull);
    const long long* e64 = (const long long*)edge;
    const int*       e32 = (const int*)edge;

    for (int e = blockIdx.x * blockDim.x + threadIdx.x; e < E;
         e += gridDim.x * blockDim.x) {
        int s, d;
        if (is64) { s = (int)e64[e]; d = (int)e64[e + E]; }
        else      { s = e32[e];      d = e32[e + E]; }
        int slot = atomicAdd(&g_cnt[d], 1);
        if (slot < PAD) g_csr[(size_t)d * PAD + slot] = s;
    }
}

__global__ void dinv_kernel(int n) {
    int i = blockIdx.x * blockDim.x + threadIdx.x;
    if (i < n) g_dinv[i] = rsqrtf((float)(g_cnt[i] + 1));  // +1 self-loop
}

// ---------------- HGEMM via mma.sync (HMMA): C = A[M,K] @ B[K,N] (+bias), fp16 in, fp16 out, fp32 accum ----
// CTA tile 128x64, BK=32. 8 warps: warpM = wid&3 (32 rows), warpN = wid>>2 (32 cols).
// Per warp: 2 m16 tiles x 4 n8 tiles x 2 k16 steps of mma.m16n8k16.
#define GBM 128
#define GBN 64
#define GBK 32
#define A_STRIDE 40   // halfs per As row (32 + 8 pad) -> conflict-free ldmatrix
#define B_STRIDE 72   // halfs per Bs row (64 + 8 pad)

__global__ __launch_bounds__(256, 2)
void hgemm_kernel(const __half* __restrict__ A, const __half* __restrict__ B,
                  const float* __restrict__ bias, __half* __restrict__ C,
                  int M, int K, int N) {
    __shared__ __half As[GBM][A_STRIDE];
    __shared__ __half Bs[GBK][B_STRIDE];

    const int tid  = threadIdx.x;
    const int wid  = tid >> 5;
    const int lane = tid & 31;
    const int warpM = wid & 3;
    const int warpN = wid >> 2;
    const int rowBase = blockIdx.x * GBM;
    const int colBase = blockIdx.y * GBN;

    // loaders
    const int arow = tid >> 1;            // 0..127
    const int acg  = (tid & 1) * 16;      // 0,16
    const int brow = tid >> 3;            // 0..31
    const int bcg  = (tid & 7) * 8;       // 0..56

    const bool aok = (rowBase + arow) < M;
    const __half* Ap = A + (size_t)(rowBase + arow) * K + acg;

    const uint4 z4 = make_uint4(0, 0, 0, 0);
    uint4 pa0 = aok ? *(const uint4*)Ap           : z4;
    uint4 pa1 = aok ? *(const uint4*)(Ap + 8)     : z4;
    uint4 pb0 = *(const uint4*)(B + (size_t)brow * N + colBase + bcg);

    float acc[2][4][4];
#pragma unroll
    for (int i = 0; i < 2; i++)
#pragma unroll
        for (int j = 0; j < 4; j++)
#pragma unroll
            for (int k = 0; k < 4; k++) acc[i][j][k] = 0.f;

    const uint32_t AsU = (uint32_t)__cvta_generic_to_shared(&As[0][0]);
    const uint32_t BsU = (uint32_t)__cvta_generic_to_shared(&Bs[0][0]);
    const uint32_t aLaneOff = (lane & 15) * (A_STRIDE * 2) + (lane >> 4) * 16;
    const uint32_t bLaneOff = (lane & 15) * (B_STRIDE * 2) + (lane >> 4) * 16;

    int k0 = 0;
    while (true) {
        *(uint4*)&As[arow][acg]     = pa0;
        *(uint4*)&As[arow][acg + 8] = pa1;
        *(uint4*)&Bs[brow][bcg]     = pb0;
        __syncthreads();

        k0 += GBK;
        const bool more = (k0 < K);
        if (more) {
            pa0 = aok ? *(const uint4*)(Ap + k0)     : z4;
            pa1 = aok ? *(const uint4*)(Ap + k0 + 8) : z4;
            pb0 = *(const uint4*)(B + (size_t)(k0 + brow) * N + colBase + bcg);
        }

#pragma unroll
        for (int ks = 0; ks < 2; ks++) {
            uint32_t a[2][4];
#pragma unroll
            for (int mi = 0; mi < 2; mi++) {
                uint32_t addr = AsU + (warpM * 32 + mi * 16) * (A_STRIDE * 2)
                              + ks * 32 + aLaneOff;
                asm volatile("ldmatrix.sync.aligned.m8n8.x4.shared.b16 {%0,%1,%2,%3}, [%4];"
                             : "=r"(a[mi][0]), "=r"(a[mi][1]), "=r"(a[mi][2]), "=r"(a[mi][3])
                             : "r"(addr));
            }
            uint32_t b[4][2];
#pragma unroll
            for (int np = 0; np < 2; np++) {
                uint32_t addr = BsU + (ks * 16) * (B_STRIDE * 2)
                              + (warpN * 32 + np * 16) * 2 + bLaneOff;
                uint32_t r0, r1, r2, r3;
                asm volatile("ldmatrix.sync.aligned.m8n8.x4.trans.shared.b16 {%0,%1,%2,%3}, [%4];"
                             : "=r"(r0), "=r"(r1), "=r"(r2), "=r"(r3)
                             : "r"(addr));
                b[np * 2][0] = r0; b[np * 2][1] = r1;
                b[np * 2 + 1][0] = r2; b[np * 2 + 1][1] = r3;
            }
#pragma unroll
            for (int mi = 0; mi < 2; mi++)
#pragma unroll
                for (int nt = 0; nt < 4; nt++) {
                    asm volatile(
                        "mma.sync.aligned.m16n8k16.row.col.f32.f16.f16.f32 "
                        "{%0,%1,%2,%3}, {%4,%5,%6,%7}, {%8,%9}, {%0,%1,%2,%3};"
                        : "+f"(acc[mi][nt][0]), "+f"(acc[mi][nt][1]),
                          "+f"(acc[mi][nt][2]), "+f"(acc[mi][nt][3])
                        : "r"(a[mi][0]), "r"(a[mi][1]), "r"(a[mi][2]), "r"(a[mi][3]),
                          "r"(b[nt][0]), "r"(b[nt][1]));
                }
        }

        if (!more) break;
        __syncthreads();
    }

    // epilogue: c0,c1 -> (row=group, col=tid4*2); c2,c3 -> row+8
    const int group = lane >> 2;
    const int tid4  = lane & 3;
#pragma unroll
    for (int mi = 0; mi < 2; mi++) {
#pragma unroll
        for (int nt = 0; nt < 4; nt++) {
            int col = colBase + warpN * 32 + nt * 8 + tid4 * 2;
            float bx = 0.f, by = 0.f;
            if (bias) { bx = bias[col]; by = bias[col + 1]; }
            int r0 = rowBase + warpM * 32 + mi * 16 + group;
            if (r0 < M) {
                __half2 h = __floats2half2_rn(acc[mi][nt][0] + bx, acc[mi][nt][1] + by);
                *(__half2*)(C + (size_t)r0 * N + col) = h;
            }
            int r1 = r0 + 8;
            if (r1 < M) {
                __half2 h = __floats2half2_rn(acc[mi][nt][2] + bx, acc[mi][nt][3] + by);
                *(__half2*)(C + (size_t)r1 * N + col) = h;
            }
        }
    }
}

// ---------------- aggregation: one warp per node, COLUMN-SPLIT passes (R11) ----------------
__device__ __forceinline__ void h4_acc(uint2 v, float w, float* acc) {
    float2 f0 = __half22float2(*(__half2*)&v.x);
    float2 f1 = __half22float2(*(__half2*)&v.y);
    acc[0] = fmaf(w, f0.x, acc[0]); acc[1] = fmaf(w, f0.y, acc[1]);
    acc[2] = fmaf(w, f1.x, acc[2]); acc[3] = fmaf(w, f1.y, acc[3]);
}

template <bool HALF_OUT>
__global__ __launch_bounds__(256)
void aggregate_kernel(const __half* __restrict__ xw,
                      const float* __restrict__ bias,
                      const __half* __restrict__ resid,  // nullable, fp16
                      void* __restrict__ outv, int n, int colOff) {
    __shared__ int   shI[8][PAD];
    __shared__ float shW[8][PAD];

    const int wslot = threadIdx.x >> 5;
    const int w     = (blockIdx.x * blockDim.x + threadIdx.x) >> 5;
    const int lane  = threadIdx.x & 31;
    if (w >= n) return;

    const int col = colOff + lane * 4;
    const float di = g_dinv[w];

    int c = g_cnt[w];
    if (c > PAD) c = PAD;

    // coalesced metadata fetch
    const int* ep = g_csr + (size_t)w * PAD;
#pragma unroll
    for (int r = 0; r < PAD / 32; r++) {
        int j = r * 32 + lane;
        if (j < c) {
            int s = ep[j];
            shI[wslot][j] = s;
            shW[wslot][j] = g_dinv[s] * di;
        }
    }
    __syncwarp();

    float acc[4] = {0.f, 0.f, 0.f, 0.f};
    h4_acc(*(const uint2*)(xw + (size_t)w * OUTD + col), di * di, acc);  // self-loop

    const int*   shi = shI[wslot];
    const float* shw = shW[wslot];
    int j = 0;
    for (; j + 4 <= c; j += 4) {
        int   s0 = shi[j],   s1 = shi[j+1], s2 = shi[j+2], s3 = shi[j+3];
        float w0 = shw[j],   w1 = shw[j+1], w2 = shw[j+2], w3 = shw[j+3];
        uint2 v0 = *(const uint2*)(xw + (size_t)s0 * OUTD + col);
        uint2 v1 = *(const uint2*)(xw + (size_t)s1 * OUTD + col);
        uint2 v2 = *(const uint2*)(xw + (size_t)s2 * OUTD + col);
        uint2 v3 = *(const uint2*)(xw + (size_t)s3 * OUTD + col);
        h4_acc(v0, w0, acc); h4_acc(v1, w1, acc);
        h4_acc(v2, w2, acc); h4_acc(v3, w3, acc);
    }
    for (; j < c; j++) {
        uint2 v = *(const uint2*)(xw + (size_t)shi[j] * OUTD + col);
        h4_acc(v, shw[j], acc);
    }

    float4 b = *(const float4*)(bias + col);
    acc[0] += b.x; acc[1] += b.y; acc[2] += b.z; acc[3] += b.w;

    if (resid) {
        uint2 q = *(const uint2*)(resid + (size_t)w * OUTD + col);
        float2 f0 = __half22float2(*(__half2*)&q.x);
        float2 f1 = __half22float2(*(__half2*)&q.y);
        acc[0] += f0.x; acc[1] += f0.y; acc[2] += f1.x; acc[3] += f1.y;
    }

#pragma unroll
    for (int k = 0; k < 4; k++) acc[k] = fmaxf(acc[k], 0.f);

    if (HALF_OUT) {
        __half* o = (__half*)outv;
        __half2 h01 = __floats2half2_rn(acc[0], acc[1]);
        __half2 h23 = __floats2half2_rn(acc[2], acc[3]);
        uint2 u; u.x = *(unsigned*)&h01; u.y = *(unsigned*)&h23;
        *(uint2*)(o + (size_t)w * OUTD + col) = u;
    } else {
        float* o = (float*)outv;
        *(float4*)(o + (size_t)w * OUTD + col) = make_float4(acc[0], acc[1], acc[2], acc[3]);
    }
}

// ---------------- launch ----------------
extern "C" void kernel_launch(void* const* d_in, const int* in_sizes, int n_in,
                              void* d_out, int out_size) {
    const float* x  = (const float*)d_in[0];
    const void*  ei = d_in[1];
    const float* W1 = (const float*)d_in[2];
    const float* b1 = (const float*)d_in[3];
    const float* W2 = (const float*)d_in[4];
    const float* b2 = (const float*)d_in[5];
    const float* Wp = (const float*)d_in[6];
    const float* bp = (const float*)d_in[7];
    float* out = (float*)d_out;

    int ind = in_sizes[2] / OUTD;     // W1 is [IN, 256]
    int n   = in_sizes[0] / ind;      // nodes
    int E   = in_sizes[1] / 2;        // edges
    if (n > MAXN) n = MAXN;
    if (E > MAXE) E = MAXE;

    __half *xwh, *idenh, *h1h, *xh, *W1h, *W2h, *Wph;
    cudaGetSymbolAddress((void**)&xwh,   g_xwh);
    cudaGetSymbolAddress((void**)&idenh, g_idenh);
    cudaGetSymbolAddress((void**)&h1h,   g_h1h);
    cudaGetSymbolAddress((void**)&xh,    g_xh);
    cudaGetSymbolAddress((void**)&W1h,   g_W1h);
    cudaGetSymbolAddress((void**)&W2h,   g_W2h);
    cudaGetSymbolAddress((void**)&Wph,   g_Wph);

    // 1. build padded CSR + degrees
    zero_cnt_kernel<<<(n + 255) / 256, 256>>>(n);
    fill_csr_kernel<<<(E + 255) / 256, 256>>>(ei, E);
    dinv_kernel<<<(n + 255) / 256, 256>>>(n);

    // 2. fp32 -> fp16 conversions (x and weights)
    int xc4 = (n * ind) / 4;
    f2h_kernel<<<(xc4 + 255) / 256, 256>>>(x, xh, xc4);
    f2h_kernel<<<(ind * OUTD / 4 + 255) / 256, 256>>>(W1, W1h, ind * OUTD / 4);
    f2h_kernel<<<(ind * OUTD / 4 + 255) / 256, 256>>>(Wp, Wph, ind * OUTD / 4);
    f2h_kernel<<<(OUTD * OUTD / 4 + 255) / 256, 256>>>(W2, W2h, OUTD * OUTD / 4);

    dim3 gg((n + GBM - 1) / GBM, OUTD / GBN);
    int aggBlocks = (n * 32 + 255) / 256;

    // 3. XW1 and projection (HMMA, fp16 out)
    hgemm_kernel<<<gg, 256>>>(xh, W1h, nullptr, xwh,   n, ind, OUTD);
    hgemm_kernel<<<gg, 256>>>(xh, Wph, bp,      idenh, n, ind, OUTD);

    // 4. conv1 aggregation + b1 + relu -> h1h (fp16), two column passes
    aggregate_kernel<true><<<aggBlocks, 256>>>(xwh, b1, nullptr, h1h, n, 0);
    aggregate_kernel<true><<<aggBlocks, 256>>>(xwh, b1, nullptr, h1h, n, 128);

    // 5. H1 @ W2 (HMMA, fp16 in/out)
    hgemm_kernel<<<gg, 256>>>(h1h, W2h, nullptr, xwh, n, OUTD, OUTD);

    // 6. conv2 aggregation + b2 + identity + relu -> out (fp32), two column passes
    aggregate_kernel<false><<<aggBlocks, 256>>>(xwh, b2, idenh, out, n, 0);
    aggregate_kernel<false><<<aggBlocks, 256>>>(xwh, b2, idenh, out, n, 128);
}